// round 10
// baseline (speedup 1.0000x reference)
#include <cuda_runtime.h>
#include <math.h>

// Problem constants (fixed shapes from reference)
#define HW     3136     // 56*56
#define HW4    784      // HW / 4 (float4 chunks per row)
#define B_SZ   64
#define C_IN   512
#define A_DIM  32
#define C_OUT  512
#define BN_EPS 1e-5f

// fc kernel dynamic smem layout (floats):
//   s_wT     : [32][513] transposed attention-weight tile
//   s_pooled : [512]
//   s_h      : [32]
#define SWT_STRIDE 513
#define SMEM_FLOATS (A_DIM * SWT_STRIDE + C_IN + A_DIM)

// Scratch for pooled means: [B, C_in]
__device__ float g_pooled[B_SZ * C_IN];

// ---------------------------------------------------------------------------
// Kernel 1: global average pool. One warp per (b, c) row, 2 independent
// float4 loads in flight (R7 config — measured fastest; 4-wide regressed
// via L1tex-queue spread). PDL trigger AFTER the load loop: the dependent
// fc launch fires only when the LAST wave's loads are done, so fc overlaps
// pool's drain without stealing SM slots during streaming.
// ---------------------------------------------------------------------------
__global__ __launch_bounds__(256) void pool_kernel(const float* __restrict__ x) {
    const int gwarp = (blockIdx.x * blockDim.x + threadIdx.x) >> 5;
    const int lane  = threadIdx.x & 31;
    if (gwarp >= B_SZ * C_IN) {
        cudaTriggerProgrammaticLaunchCompletion();
        return;
    }

    const float4* __restrict__ row =
        reinterpret_cast<const float4*>(x + (size_t)gwarp * HW);

    float s0 = 0.f, s1 = 0.f;
    int i = lane;
    #pragma unroll 4
    for (; i + 32 < HW4; i += 64) {
        float4 v0 = __ldg(&row[i]);
        float4 v1 = __ldg(&row[i + 32]);
        s0 += (v0.x + v0.y) + (v0.z + v0.w);
        s1 += (v1.x + v1.y) + (v1.z + v1.w);
    }
    if (i < HW4) {
        float4 v0 = __ldg(&row[i]);
        s0 += (v0.x + v0.y) + (v0.z + v0.w);
    }

    // All loads issued; fire the programmatic edge (launch happens when
    // every block has triggered, i.e. during the final wave's drain).
    cudaTriggerProgrammaticLaunchCompletion();

    float s = s0 + s1;
    #pragma unroll
    for (int off = 16; off > 0; off >>= 1)
        s += __shfl_xor_sync(0xFFFFFFFFu, s, off);

    if (lane == 0)
        g_pooled[gwarp] = s * (1.0f / (float)HW);
}

// ---------------------------------------------------------------------------
// Kernel 2: FC chain (R7 structure — best measured). Grid = 128 blocks:
// block (b, t), t=0 channel / t=1 filter. 512 threads, one output each.
// Weight tile staged into smem transposed via coalesced float4 loads;
// everything before cudaGridDependencySynchronize() overlaps pool's drain.
// ---------------------------------------------------------------------------
__global__ __launch_bounds__(512) void fc_kernel(
    const float* __restrict__ fc_w,         // [A, C_in]
    const float* __restrict__ bn_gamma,     // [A]
    const float* __restrict__ bn_beta,      // [A]
    const float* __restrict__ bn_mean,      // [A]
    const float* __restrict__ bn_var,       // [A]
    const float* __restrict__ channel_fc_w, // [C_in, A]
    const float* __restrict__ channel_fc_b, // [C_in]
    const float* __restrict__ filter_fc_w,  // [C_out, A]
    const float* __restrict__ filter_fc_b,  // [C_out]
    float* __restrict__ out)                // [2 * B * 512]
{
    extern __shared__ __align__(16) float smem[];
    float* s_wT     = smem;                          // [32][513]
    float* s_pooled = smem + A_DIM * SWT_STRIDE;     // [512]
    float* s_h      = s_pooled + C_IN;               // [32]

    const int b    = blockIdx.x >> 1;
    const int t    = blockIdx.x & 1;        // 0 = channel, 1 = filter
    const int tid  = threadIdx.x;
    const int warp = tid >> 5;
    const int lane = tid & 31;

    // ======== PREAMBLE (overlaps pool's drain via PDL trigger) ========
    const float* __restrict__ w_mat  = t ? filter_fc_w : channel_fc_w;
    const float* __restrict__ w_bias = t ? filter_fc_b : channel_fc_b;
    const float4* __restrict__ g4 = reinterpret_cast<const float4*>(w_mat);
    #pragma unroll
    for (int k = 0; k < 8; ++k) {
        const int i = tid + k * 512;         // float4 index, lanes contiguous
        float4 v = __ldg(&g4[i]);
        const int f = i << 2;                // first float index
        const int c = f >> 5;                // output row (0..511)
        const int a = f & 31;                // a-offset (multiple of 4)
        s_wT[(a + 0) * SWT_STRIDE + c] = v.x;
        s_wT[(a + 1) * SWT_STRIDE + c] = v.y;
        s_wT[(a + 2) * SWT_STRIDE + c] = v.z;
        s_wT[(a + 3) * SWT_STRIDE + c] = v.w;
    }
    float bias = __ldg(&w_bias[tid]);

    // fc_w rows for this warp's two h-dots (coalesced, 4 lines per LDG)
    const int a0 = warp, a1 = warp + 16;
    const float4* __restrict__ f0 =
        reinterpret_cast<const float4*>(fc_w + a0 * C_IN);
    const float4* __restrict__ f1 =
        reinterpret_cast<const float4*>(fc_w + a1 * C_IN);
    float4 fw00 = __ldg(&f0[lane]);      float4 fw01 = __ldg(&f0[lane + 32]);
    float4 fw02 = __ldg(&f0[lane + 64]); float4 fw03 = __ldg(&f0[lane + 96]);
    float4 fw10 = __ldg(&f1[lane]);      float4 fw11 = __ldg(&f1[lane + 32]);
    float4 fw12 = __ldg(&f1[lane + 64]); float4 fw13 = __ldg(&f1[lane + 96]);

    float bnv0 = __ldg(&bn_var[a0]),   bnv1 = __ldg(&bn_var[a1]);
    float bnm0 = __ldg(&bn_mean[a0]),  bnm1 = __ldg(&bn_mean[a1]);
    float bng0 = __ldg(&bn_gamma[a0]), bng1 = __ldg(&bn_gamma[a1]);
    float bnb0 = __ldg(&bn_beta[a0]),  bnb1 = __ldg(&bn_beta[a1]);

    // ======== wait for pool_kernel results (programmatic edge) ========
    cudaGridDependencySynchronize();

    s_pooled[tid] = g_pooled[b * C_IN + tid];
    __syncthreads();

    // ---- h: warp-parallel dots with pre-loaded fc_w ----
    const float4* __restrict__ sp4 = reinterpret_cast<const float4*>(s_pooled);
    float4 pv0 = sp4[lane];      float4 pv1 = sp4[lane + 32];
    float4 pv2 = sp4[lane + 64]; float4 pv3 = sp4[lane + 96];

    float acc0 = 0.f, acc1 = 0.f;
    acc0 = fmaf(fw00.x, pv0.x, acc0); acc0 = fmaf(fw00.y, pv0.y, acc0);
    acc0 = fmaf(fw00.z, pv0.z, acc0); acc0 = fmaf(fw00.w, pv0.w, acc0);
    acc0 = fmaf(fw01.x, pv1.x, acc0); acc0 = fmaf(fw01.y, pv1.y, acc0);
    acc0 = fmaf(fw01.z, pv1.z, acc0); acc0 = fmaf(fw01.w, pv1.w, acc0);
    acc0 = fmaf(fw02.x, pv2.x, acc0); acc0 = fmaf(fw02.y, pv2.y, acc0);
    acc0 = fmaf(fw02.z, pv2.z, acc0); acc0 = fmaf(fw02.w, pv2.w, acc0);
    acc0 = fmaf(fw03.x, pv3.x, acc0); acc0 = fmaf(fw03.y, pv3.y, acc0);
    acc0 = fmaf(fw03.z, pv3.z, acc0); acc0 = fmaf(fw03.w, pv3.w, acc0);

    acc1 = fmaf(fw10.x, pv0.x, acc1); acc1 = fmaf(fw10.y, pv0.y, acc1);
    acc1 = fmaf(fw10.z, pv0.z, acc1); acc1 = fmaf(fw10.w, pv0.w, acc1);
    acc1 = fmaf(fw11.x, pv1.x, acc1); acc1 = fmaf(fw11.y, pv1.y, acc1);
    acc1 = fmaf(fw11.z, pv1.z, acc1); acc1 = fmaf(fw11.w, pv1.w, acc1);
    acc1 = fmaf(fw12.x, pv2.x, acc1); acc1 = fmaf(fw12.y, pv2.y, acc1);
    acc1 = fmaf(fw12.z, pv2.z, acc1); acc1 = fmaf(fw12.w, pv2.w, acc1);
    acc1 = fmaf(fw13.x, pv3.x, acc1); acc1 = fmaf(fw13.y, pv3.y, acc1);
    acc1 = fmaf(fw13.z, pv3.z, acc1); acc1 = fmaf(fw13.w, pv3.w, acc1);

    #pragma unroll
    for (int off = 16; off > 0; off >>= 1) {
        acc0 += __shfl_xor_sync(0xFFFFFFFFu, acc0, off);
        acc1 += __shfl_xor_sync(0xFFFFFFFFu, acc1, off);
    }
    if (lane == 0) {
        float h0 = (acc0 - bnm0) * (bng0 * rsqrtf(bnv0 + BN_EPS)) + bnb0;
        float h1 = (acc1 - bnm1) * (bng1 * rsqrtf(bnv1 + BN_EPS)) + bnb1;
        s_h[a0] = fmaxf(h0, 0.f);
        s_h[a1] = fmaxf(h1, 0.f);
    }
    __syncthreads();

    // ---- attention output: dot over smem-transposed weights ----
    float acc = bias;
    #pragma unroll
    for (int a = 0; a < A_DIM; ++a)
        acc = fmaf(s_h[a], s_wT[a * SWT_STRIDE + tid], acc);

    // fast sigmoid: MUFU-based exp + fast reciprocal (rel err ~1e-7,
    // budget is 1e-3)
    out[(size_t)t * (B_SZ * C_IN) + b * C_IN + tid] =
        __fdividef(1.0f, 1.0f + __expf(-acc));
}

extern "C" void kernel_launch(void* const* d_in, const int* in_sizes, int n_in,
                              void* d_out, int out_size) {
    const float* x            = (const float*)d_in[0];
    const float* fc_w         = (const float*)d_in[1];
    const float* bn_gamma     = (const float*)d_in[2];
    const float* bn_beta      = (const float*)d_in[3];
    const float* bn_mean      = (const float*)d_in[4];
    const float* bn_var       = (const float*)d_in[5];
    const float* channel_fc_w = (const float*)d_in[6];
    const float* channel_fc_b = (const float*)d_in[7];
    const float* filter_fc_w  = (const float*)d_in[8];
    const float* filter_fc_b  = (const float*)d_in[9];
    float* out = (float*)d_out;

    const int smem_bytes = SMEM_FLOATS * (int)sizeof(float);
    static bool attr_set = false;   // host-side only; idempotent runtime attr
    if (!attr_set) {
        cudaFuncSetAttribute(fc_kernel,
                             cudaFuncAttributeMaxDynamicSharedMemorySize,
                             smem_bytes);
        attr_set = true;
    }

    pool_kernel<<<(B_SZ * C_IN) / 8, 256>>>(x);

    cudaLaunchConfig_t cfg = {};
    cfg.gridDim  = dim3(B_SZ * 2);
    cfg.blockDim = dim3(512);
    cfg.dynamicSmemBytes = smem_bytes;
    cfg.stream = 0;
    cudaLaunchAttribute attr[1];
    attr[0].id = cudaLaunchAttributeProgrammaticStreamSerialization;
    attr[0].val.programmaticStreamSerializationAllowed = 1;
    cfg.attrs = attr;
    cfg.numAttrs = 1;
    cudaLaunchKernelEx(&cfg, fc_kernel,
                       fc_w, bn_gamma, bn_beta, bn_mean, bn_var,
                       channel_fc_w, channel_fc_b,
                       filter_fc_w, filter_fc_b, out);
}

// round 11
// speedup vs baseline: 1.0042x; 1.0042x over previous
#include <cuda_runtime.h>
#include <math.h>

// Problem constants (fixed shapes from reference)
#define HW     3136     // 56*56
#define HW4    784      // HW / 4 (float4 chunks per row)
#define B_SZ   64
#define C_IN   512
#define A_DIM  32
#define C_OUT  512
#define BN_EPS 1e-5f
#define POOL_BLOCKS ((B_SZ * C_IN) / 8)   // 4096

// fc kernel dynamic smem layout (floats):
//   s_wT     : [32][513] transposed attention-weight tile
//   s_pooled : [512]
//   s_h      : [32]
#define SWT_STRIDE 513
#define SMEM_FLOATS (A_DIM * SWT_STRIDE + C_IN + A_DIM)

// Scratch for pooled means: [B, C_in]
__device__ float g_pooled[B_SZ * C_IN];

__device__ __forceinline__ void l2_prefetch(const void* p) {
    asm volatile("prefetch.global.L2 [%0];" :: "l"(p));
}

// ---------------------------------------------------------------------------
// Kernel 1: global average pool. One warp per (b, c) row, 2 independent
// float4 loads in flight (measured fastest across 2/4-wide variants).
// Last-wave blocks (blockIdx >= 4032) additionally L2-prefetch the FC
// weights at the END of their work — they finish last, so the ~197KB of
// weights are L2-resident exactly when fc_kernel launches, converting fc's
// serialized cold-DRAM trips (~1.1us each) into L2 hits.
// ---------------------------------------------------------------------------
__global__ __launch_bounds__(256) void pool_kernel(
    const float* __restrict__ x,
    const float* __restrict__ fc_w,         // 64KB
    const float* __restrict__ channel_fc_w, // 64KB
    const float* __restrict__ filter_fc_w,  // 64KB
    const float* __restrict__ channel_fc_b, // 2KB
    const float* __restrict__ filter_fc_b,  // 2KB
    const float* __restrict__ bn_gamma,     // 128B each
    const float* __restrict__ bn_beta,
    const float* __restrict__ bn_mean,
    const float* __restrict__ bn_var)
{
    const int gwarp = (blockIdx.x * blockDim.x + threadIdx.x) >> 5;
    const int lane  = threadIdx.x & 31;

    const float4* __restrict__ row =
        reinterpret_cast<const float4*>(x + (size_t)gwarp * HW);

    float s0 = 0.f, s1 = 0.f;
    int i = lane;
    #pragma unroll 4
    for (; i + 32 < HW4; i += 64) {
        float4 v0 = __ldg(&row[i]);
        float4 v1 = __ldg(&row[i + 32]);
        s0 += (v0.x + v0.y) + (v0.z + v0.w);
        s1 += (v1.x + v1.y) + (v1.z + v1.w);
    }
    if (i < HW4) {
        float4 v0 = __ldg(&row[i]);
        s0 += (v0.x + v0.y) + (v0.z + v0.w);
    }
    float s = s0 + s1;

    #pragma unroll
    for (int off = 16; off > 0; off >>= 1)
        s += __shfl_xor_sync(0xFFFFFFFFu, s, off);

    if (lane == 0)
        g_pooled[gwarp] = s * (1.0f / (float)HW);

    // ---- L2 warm-up of FC inputs by the last-finishing blocks ----
    if (blockIdx.x >= POOL_BLOCKS - 64) {
        const int tid = threadIdx.x;
        // 64KB arrays: 512 lines of 128B; 256 threads -> 2 lines each
        #pragma unroll
        for (int k = 0; k < 2; ++k) {
            const int line = tid + k * 256;
            l2_prefetch((const char*)fc_w         + line * 128);
            l2_prefetch((const char*)channel_fc_w + line * 128);
            l2_prefetch((const char*)filter_fc_w  + line * 128);
        }
        // 2KB biases: 16 lines each
        if (tid < 16) {
            l2_prefetch((const char*)channel_fc_b + tid * 128);
            l2_prefetch((const char*)filter_fc_b  + tid * 128);
        }
        // bn params: 128B each
        if (tid == 0) {
            l2_prefetch(bn_gamma);
            l2_prefetch(bn_beta);
            l2_prefetch(bn_mean);
            l2_prefetch(bn_var);
        }
    }
}

// ---------------------------------------------------------------------------
// Kernel 2: FC chain (R7 structure — best measured). Grid = 128 blocks:
// block (b, t), t=0 channel / t=1 filter. 512 threads, one output each.
// Weight tile staged into smem transposed via coalesced float4 loads.
// ---------------------------------------------------------------------------
__global__ __launch_bounds__(512) void fc_kernel(
    const float* __restrict__ fc_w,         // [A, C_in]
    const float* __restrict__ bn_gamma,     // [A]
    const float* __restrict__ bn_beta,      // [A]
    const float* __restrict__ bn_mean,      // [A]
    const float* __restrict__ bn_var,       // [A]
    const float* __restrict__ channel_fc_w, // [C_in, A]
    const float* __restrict__ channel_fc_b, // [C_in]
    const float* __restrict__ filter_fc_w,  // [C_out, A]
    const float* __restrict__ filter_fc_b,  // [C_out]
    float* __restrict__ out)                // [2 * B * 512]
{
    extern __shared__ __align__(16) float smem[];
    float* s_wT     = smem;                          // [32][513]
    float* s_pooled = smem + A_DIM * SWT_STRIDE;     // [512]
    float* s_h      = s_pooled + C_IN;               // [32]

    const int b    = blockIdx.x >> 1;
    const int t    = blockIdx.x & 1;        // 0 = channel, 1 = filter
    const int tid  = threadIdx.x;
    const int warp = tid >> 5;
    const int lane = tid & 31;

    // ======== stage attention weight tile (L2-hot via pool prefetch) ========
    const float* __restrict__ w_mat  = t ? filter_fc_w : channel_fc_w;
    const float* __restrict__ w_bias = t ? filter_fc_b : channel_fc_b;
    const float4* __restrict__ g4 = reinterpret_cast<const float4*>(w_mat);
    #pragma unroll
    for (int k = 0; k < 8; ++k) {
        const int i = tid + k * 512;         // float4 index, lanes contiguous
        float4 v = __ldg(&g4[i]);
        const int f = i << 2;                // first float index
        const int c = f >> 5;                // output row (0..511)
        const int a = f & 31;                // a-offset (multiple of 4)
        s_wT[(a + 0) * SWT_STRIDE + c] = v.x;
        s_wT[(a + 1) * SWT_STRIDE + c] = v.y;
        s_wT[(a + 2) * SWT_STRIDE + c] = v.z;
        s_wT[(a + 3) * SWT_STRIDE + c] = v.w;
    }
    float bias = __ldg(&w_bias[tid]);

    // fc_w rows for this warp's two h-dots (coalesced, 4 lines per LDG)
    const int a0 = warp, a1 = warp + 16;
    const float4* __restrict__ f0 =
        reinterpret_cast<const float4*>(fc_w + a0 * C_IN);
    const float4* __restrict__ f1 =
        reinterpret_cast<const float4*>(fc_w + a1 * C_IN);
    float4 fw00 = __ldg(&f0[lane]);      float4 fw01 = __ldg(&f0[lane + 32]);
    float4 fw02 = __ldg(&f0[lane + 64]); float4 fw03 = __ldg(&f0[lane + 96]);
    float4 fw10 = __ldg(&f1[lane]);      float4 fw11 = __ldg(&f1[lane + 32]);
    float4 fw12 = __ldg(&f1[lane + 64]); float4 fw13 = __ldg(&f1[lane + 96]);

    float bnv0 = __ldg(&bn_var[a0]),   bnv1 = __ldg(&bn_var[a1]);
    float bnm0 = __ldg(&bn_mean[a0]),  bnm1 = __ldg(&bn_mean[a1]);
    float bng0 = __ldg(&bn_gamma[a0]), bng1 = __ldg(&bn_gamma[a1]);
    float bnb0 = __ldg(&bn_beta[a0]),  bnb1 = __ldg(&bn_beta[a1]);

    // pooled row (L2-hot, just written by pool_kernel)
    s_pooled[tid] = g_pooled[b * C_IN + tid];
    __syncthreads();

    // ---- h: warp-parallel dots with pre-loaded fc_w ----
    const float4* __restrict__ sp4 = reinterpret_cast<const float4*>(s_pooled);
    float4 pv0 = sp4[lane];      float4 pv1 = sp4[lane + 32];
    float4 pv2 = sp4[lane + 64]; float4 pv3 = sp4[lane + 96];

    float acc0 = 0.f, acc1 = 0.f;
    acc0 = fmaf(fw00.x, pv0.x, acc0); acc0 = fmaf(fw00.y, pv0.y, acc0);
    acc0 = fmaf(fw00.z, pv0.z, acc0); acc0 = fmaf(fw00.w, pv0.w, acc0);
    acc0 = fmaf(fw01.x, pv1.x, acc0); acc0 = fmaf(fw01.y, pv1.y, acc0);
    acc0 = fmaf(fw01.z, pv1.z, acc0); acc0 = fmaf(fw01.w, pv1.w, acc0);
    acc0 = fmaf(fw02.x, pv2.x, acc0); acc0 = fmaf(fw02.y, pv2.y, acc0);
    acc0 = fmaf(fw02.z, pv2.z, acc0); acc0 = fmaf(fw02.w, pv2.w, acc0);
    acc0 = fmaf(fw03.x, pv3.x, acc0); acc0 = fmaf(fw03.y, pv3.y, acc0);
    acc0 = fmaf(fw03.z, pv3.z, acc0); acc0 = fmaf(fw03.w, pv3.w, acc0);

    acc1 = fmaf(fw10.x, pv0.x, acc1); acc1 = fmaf(fw10.y, pv0.y, acc1);
    acc1 = fmaf(fw10.z, pv0.z, acc1); acc1 = fmaf(fw10.w, pv0.w, acc1);
    acc1 = fmaf(fw11.x, pv1.x, acc1); acc1 = fmaf(fw11.y, pv1.y, acc1);
    acc1 = fmaf(fw11.z, pv1.z, acc1); acc1 = fmaf(fw11.w, pv1.w, acc1);
    acc1 = fmaf(fw12.x, pv2.x, acc1); acc1 = fmaf(fw12.y, pv2.y, acc1);
    acc1 = fmaf(fw12.z, pv2.z, acc1); acc1 = fmaf(fw12.w, pv2.w, acc1);
    acc1 = fmaf(fw13.x, pv3.x, acc1); acc1 = fmaf(fw13.y, pv3.y, acc1);
    acc1 = fmaf(fw13.z, pv3.z, acc1); acc1 = fmaf(fw13.w, pv3.w, acc1);

    #pragma unroll
    for (int off = 16; off > 0; off >>= 1) {
        acc0 += __shfl_xor_sync(0xFFFFFFFFu, acc0, off);
        acc1 += __shfl_xor_sync(0xFFFFFFFFu, acc1, off);
    }
    if (lane == 0) {
        float h0 = (acc0 - bnm0) * (bng0 * rsqrtf(bnv0 + BN_EPS)) + bnb0;
        float h1 = (acc1 - bnm1) * (bng1 * rsqrtf(bnv1 + BN_EPS)) + bnb1;
        s_h[a0] = fmaxf(h0, 0.f);
        s_h[a1] = fmaxf(h1, 0.f);
    }
    __syncthreads();

    // ---- attention output: dot over smem-transposed weights ----
    float acc = bias;
    #pragma unroll
    for (int a = 0; a < A_DIM; ++a)
        acc = fmaf(s_h[a], s_wT[a * SWT_STRIDE + tid], acc);

    // fast sigmoid (MUFU.EX2 + fast rcp): rel err ~1e-7, budget 1e-3
    out[(size_t)t * (B_SZ * C_IN) + b * C_IN + tid] =
        __fdividef(1.0f, 1.0f + __expf(-acc));
}

extern "C" void kernel_launch(void* const* d_in, const int* in_sizes, int n_in,
                              void* d_out, int out_size) {
    const float* x            = (const float*)d_in[0];
    const float* fc_w         = (const float*)d_in[1];
    const float* bn_gamma     = (const float*)d_in[2];
    const float* bn_beta      = (const float*)d_in[3];
    const float* bn_mean      = (const float*)d_in[4];
    const float* bn_var       = (const float*)d_in[5];
    const float* channel_fc_w = (const float*)d_in[6];
    const float* channel_fc_b = (const float*)d_in[7];
    const float* filter_fc_w  = (const float*)d_in[8];
    const float* filter_fc_b  = (const float*)d_in[9];
    float* out = (float*)d_out;

    const int smem_bytes = SMEM_FLOATS * (int)sizeof(float);
    static bool attr_set = false;   // host-side only; idempotent runtime attr
    if (!attr_set) {
        cudaFuncSetAttribute(fc_kernel,
                             cudaFuncAttributeMaxDynamicSharedMemorySize,
                             smem_bytes);
        attr_set = true;
    }

    pool_kernel<<<POOL_BLOCKS, 256>>>(x, fc_w, channel_fc_w, filter_fc_w,
                                      channel_fc_b, filter_fc_b,
                                      bn_gamma, bn_beta, bn_mean, bn_var);

    fc_kernel<<<B_SZ * 2, 512, smem_bytes>>>(
        fc_w, bn_gamma, bn_beta, bn_mean, bn_var,
        channel_fc_w, channel_fc_b, filter_fc_w, filter_fc_b, out);
}

// round 12
// speedup vs baseline: 1.0047x; 1.0005x over previous
#include <cuda_runtime.h>
#include <math.h>
#include <cstdint>

// Problem constants (fixed shapes from reference)
#define HW     3136     // 56*56
#define HW4    784      // HW / 4 (float4 chunks per row)
#define B_SZ   64
#define C_IN   512
#define A_DIM  32
#define C_OUT  512
#define BN_EPS 1e-5f
#define POOL_BLOCKS ((B_SZ * C_IN) / 8)   // 4096

// fc smem layout (floats):
//   s_lin    : 16384  raw attention tile (cp.async dest)
//   s_wT     : 32*513 transposed attention tile
//   s_pooled : 512
//   s_bias   : 512
//   s_bn     : 128  [gamma | beta | mean | var] x 32
//   s_h      : 32
#define SWT_STRIDE 513
#define SMEM_FLOATS (16384 + A_DIM * SWT_STRIDE + C_IN + C_IN + 128 + A_DIM)

// Scratch for pooled means: [B, C_in]
__device__ float g_pooled[B_SZ * C_IN];

__device__ __forceinline__ void l2_prefetch(const void* p) {
    asm volatile("prefetch.global.L2 [%0];" :: "l"(p));
}
__device__ __forceinline__ void cp_async16(uint32_t dst_smem, const void* src) {
    asm volatile("cp.async.cg.shared.global [%0], [%1], 16;"
                 :: "r"(dst_smem), "l"(src));
}

// ---------------------------------------------------------------------------
// Kernel 1: global average pool (R7/R11 config — near HBM floor).
// Last-wave blocks L2-prefetch FC inputs (cheap, keeps weights L2-hot).
// ---------------------------------------------------------------------------
__global__ __launch_bounds__(256) void pool_kernel(
    const float* __restrict__ x,
    const float* __restrict__ fc_w,
    const float* __restrict__ channel_fc_w,
    const float* __restrict__ filter_fc_w,
    const float* __restrict__ channel_fc_b,
    const float* __restrict__ filter_fc_b,
    const float* __restrict__ bn_gamma,
    const float* __restrict__ bn_beta,
    const float* __restrict__ bn_mean,
    const float* __restrict__ bn_var)
{
    const int gwarp = (blockIdx.x * blockDim.x + threadIdx.x) >> 5;
    const int lane  = threadIdx.x & 31;

    const float4* __restrict__ row =
        reinterpret_cast<const float4*>(x + (size_t)gwarp * HW);

    float s0 = 0.f, s1 = 0.f;
    int i = lane;
    #pragma unroll 4
    for (; i + 32 < HW4; i += 64) {
        float4 v0 = __ldg(&row[i]);
        float4 v1 = __ldg(&row[i + 32]);
        s0 += (v0.x + v0.y) + (v0.z + v0.w);
        s1 += (v1.x + v1.y) + (v1.z + v1.w);
    }
    if (i < HW4) {
        float4 v0 = __ldg(&row[i]);
        s0 += (v0.x + v0.y) + (v0.z + v0.w);
    }
    float s = s0 + s1;

    #pragma unroll
    for (int off = 16; off > 0; off >>= 1)
        s += __shfl_xor_sync(0xFFFFFFFFu, s, off);

    if (lane == 0)
        g_pooled[gwarp] = s * (1.0f / (float)HW);

    if (blockIdx.x >= POOL_BLOCKS - 64) {
        const int tid = threadIdx.x;
        #pragma unroll
        for (int k = 0; k < 2; ++k) {
            const int line = tid + k * 256;
            l2_prefetch((const char*)fc_w         + line * 128);
            l2_prefetch((const char*)channel_fc_w + line * 128);
            l2_prefetch((const char*)filter_fc_w  + line * 128);
        }
        if (tid < 16) {
            l2_prefetch((const char*)channel_fc_b + tid * 128);
            l2_prefetch((const char*)filter_fc_b  + tid * 128);
        }
        if (tid == 0) {
            l2_prefetch(bn_gamma); l2_prefetch(bn_beta);
            l2_prefetch(bn_mean);  l2_prefetch(bn_var);
        }
    }
}

// ---------------------------------------------------------------------------
// Kernel 2: FC chain. Grid = 128 blocks: block (b, t). 512 threads.
// ALL small inputs staged via cp.async (zero register footprint -> every
// copy in flight at once, one wait = ~one memory latency). fc_w rows kept
// in registers: with the tile out of the register budget, ptxas can hoist
// all 8 LDG.128s. Then smem->smem transpose + compute.
// ---------------------------------------------------------------------------
__global__ __launch_bounds__(512) void fc_kernel(
    const float* __restrict__ fc_w,         // [A, C_in]
    const float* __restrict__ bn_gamma,     // [A]
    const float* __restrict__ bn_beta,      // [A]
    const float* __restrict__ bn_mean,      // [A]
    const float* __restrict__ bn_var,       // [A]
    const float* __restrict__ channel_fc_w, // [C_in, A]
    const float* __restrict__ channel_fc_b, // [C_in]
    const float* __restrict__ filter_fc_w,  // [C_out, A]
    const float* __restrict__ filter_fc_b,  // [C_out]
    float* __restrict__ out)                // [2 * B * 512]
{
    extern __shared__ __align__(16) float smem[];
    float* s_lin    = smem;                           // 16384
    float* s_wT     = smem + 16384;                   // 32*513
    float* s_pooled = s_wT + A_DIM * SWT_STRIDE;      // 512
    float* s_bias   = s_pooled + C_IN;                // 512
    float* s_bn     = s_bias + C_IN;                  // 128
    float* s_h      = s_bn + 128;                     // 32

    const int b    = blockIdx.x >> 1;
    const int t    = blockIdx.x & 1;        // 0 = channel, 1 = filter
    const int tid  = threadIdx.x;
    const int warp = tid >> 5;
    const int lane = tid & 31;

    const float* __restrict__ w_mat  = t ? filter_fc_w : channel_fc_w;
    const float* __restrict__ w_bias = t ? filter_fc_b : channel_fc_b;

    // ---- fc_w rows for this warp's two h-dots: register loads, hoisted ----
    const int a0 = warp, a1 = warp + 16;
    const float4* __restrict__ f0 =
        reinterpret_cast<const float4*>(fc_w + a0 * C_IN);
    const float4* __restrict__ f1 =
        reinterpret_cast<const float4*>(fc_w + a1 * C_IN);
    float4 fw00 = __ldg(&f0[lane]);      float4 fw01 = __ldg(&f0[lane + 32]);
    float4 fw02 = __ldg(&f0[lane + 64]); float4 fw03 = __ldg(&f0[lane + 96]);
    float4 fw10 = __ldg(&f1[lane]);      float4 fw11 = __ldg(&f1[lane + 32]);
    float4 fw12 = __ldg(&f1[lane + 64]); float4 fw13 = __ldg(&f1[lane + 96]);

    // ---- cp.async staging: tile + pooled + bias + bn, all in flight ----
    const uint32_t s_lin_a    = (uint32_t)__cvta_generic_to_shared(s_lin);
    const uint32_t s_pooled_a = (uint32_t)__cvta_generic_to_shared(s_pooled);
    const uint32_t s_bias_a   = (uint32_t)__cvta_generic_to_shared(s_bias);
    const uint32_t s_bn_a     = (uint32_t)__cvta_generic_to_shared(s_bn);

    #pragma unroll
    for (int k = 0; k < 8; ++k) {
        const int i = tid + k * 512;              // float4 index
        cp_async16(s_lin_a + i * 16, w_mat + i * 4);
    }
    if (tid < 128) {
        cp_async16(s_pooled_a + tid * 16, g_pooled + b * C_IN + tid * 4);
    } else if (tid < 256) {
        const int j = tid - 128;
        cp_async16(s_bias_a + j * 16, w_bias + j * 4);
    } else if (tid < 264) {
        const int j = tid - 256;
        cp_async16(s_bn_a + j * 16, bn_gamma + j * 4);          // [0,32)
    } else if (tid < 272) {
        const int j = tid - 264;
        cp_async16(s_bn_a + 128 + j * 16, bn_beta + j * 4);     // [32,64)
    } else if (tid < 280) {
        const int j = tid - 272;
        cp_async16(s_bn_a + 256 + j * 16, bn_mean + j * 4);     // [64,96)
    } else if (tid < 288) {
        const int j = tid - 280;
        cp_async16(s_bn_a + 384 + j * 16, bn_var + j * 4);      // [96,128)
    }
    asm volatile("cp.async.commit_group;");
    asm volatile("cp.async.wait_group 0;");
    __syncthreads();

    // ---- transpose s_lin -> s_wT (both sides conflict-free) ----
    #pragma unroll
    for (int k = 0; k < 8; ++k) {
        const int i = tid + k * 512;
        float4 v = *reinterpret_cast<const float4*>(s_lin + i * 4);
        const int f = i << 2;
        const int c = f >> 5;                // output row (0..511)
        const int a = f & 31;                // a-offset (multiple of 4)
        s_wT[(a + 0) * SWT_STRIDE + c] = v.x;
        s_wT[(a + 1) * SWT_STRIDE + c] = v.y;
        s_wT[(a + 2) * SWT_STRIDE + c] = v.z;
        s_wT[(a + 3) * SWT_STRIDE + c] = v.w;
    }

    // ---- h: warp-parallel dots (fc_w in regs, pooled in smem) ----
    const float4* __restrict__ sp4 = reinterpret_cast<const float4*>(s_pooled);
    float4 pv0 = sp4[lane];      float4 pv1 = sp4[lane + 32];
    float4 pv2 = sp4[lane + 64]; float4 pv3 = sp4[lane + 96];

    float acc0 = 0.f, acc1 = 0.f;
    acc0 = fmaf(fw00.x, pv0.x, acc0); acc0 = fmaf(fw00.y, pv0.y, acc0);
    acc0 = fmaf(fw00.z, pv0.z, acc0); acc0 = fmaf(fw00.w, pv0.w, acc0);
    acc0 = fmaf(fw01.x, pv1.x, acc0); acc0 = fmaf(fw01.y, pv1.y, acc0);
    acc0 = fmaf(fw01.z, pv1.z, acc0); acc0 = fmaf(fw01.w, pv1.w, acc0);
    acc0 = fmaf(fw02.x, pv2.x, acc0); acc0 = fmaf(fw02.y, pv2.y, acc0);
    acc0 = fmaf(fw02.z, pv2.z, acc0); acc0 = fmaf(fw02.w, pv2.w, acc0);
    acc0 = fmaf(fw03.x, pv3.x, acc0); acc0 = fmaf(fw03.y, pv3.y, acc0);
    acc0 = fmaf(fw03.z, pv3.z, acc0); acc0 = fmaf(fw03.w, pv3.w, acc0);

    acc1 = fmaf(fw10.x, pv0.x, acc1); acc1 = fmaf(fw10.y, pv0.y, acc1);
    acc1 = fmaf(fw10.z, pv0.z, acc1); acc1 = fmaf(fw10.w, pv0.w, acc1);
    acc1 = fmaf(fw11.x, pv1.x, acc1); acc1 = fmaf(fw11.y, pv1.y, acc1);
    acc1 = fmaf(fw11.z, pv1.z, acc1); acc1 = fmaf(fw11.w, pv1.w, acc1);
    acc1 = fmaf(fw12.x, pv2.x, acc1); acc1 = fmaf(fw12.y, pv2.y, acc1);
    acc1 = fmaf(fw12.z, pv2.z, acc1); acc1 = fmaf(fw12.w, pv2.w, acc1);
    acc1 = fmaf(fw13.x, pv3.x, acc1); acc1 = fmaf(fw13.y, pv3.y, acc1);
    acc1 = fmaf(fw13.z, pv3.z, acc1); acc1 = fmaf(fw13.w, pv3.w, acc1);

    #pragma unroll
    for (int off = 16; off > 0; off >>= 1) {
        acc0 += __shfl_xor_sync(0xFFFFFFFFu, acc0, off);
        acc1 += __shfl_xor_sync(0xFFFFFFFFu, acc1, off);
    }
    if (lane == 0) {
        float h0 = (acc0 - s_bn[64 + a0]) *
                   (s_bn[a0] * rsqrtf(s_bn[96 + a0] + BN_EPS)) + s_bn[32 + a0];
        float h1 = (acc1 - s_bn[64 + a1]) *
                   (s_bn[a1] * rsqrtf(s_bn[96 + a1] + BN_EPS)) + s_bn[32 + a1];
        s_h[a0] = fmaxf(h0, 0.f);
        s_h[a1] = fmaxf(h1, 0.f);
    }
    __syncthreads();

    // ---- attention output: dot over smem-transposed weights ----
    float acc = s_bias[tid];
    #pragma unroll
    for (int a = 0; a < A_DIM; ++a)
        acc = fmaf(s_h[a], s_wT[a * SWT_STRIDE + tid], acc);

    // fast sigmoid (MUFU.EX2 + fast rcp): rel err ~1e-7, budget 1e-3
    out[(size_t)t * (B_SZ * C_IN) + b * C_IN + tid] =
        __fdividef(1.0f, 1.0f + __expf(-acc));
}

extern "C" void kernel_launch(void* const* d_in, const int* in_sizes, int n_in,
                              void* d_out, int out_size) {
    const float* x            = (const float*)d_in[0];
    const float* fc_w         = (const float*)d_in[1];
    const float* bn_gamma     = (const float*)d_in[2];
    const float* bn_beta      = (const float*)d_in[3];
    const float* bn_mean      = (const float*)d_in[4];
    const float* bn_var       = (const float*)d_in[5];
    const float* channel_fc_w = (const float*)d_in[6];
    const float* channel_fc_b = (const float*)d_in[7];
    const float* filter_fc_w  = (const float*)d_in[8];
    const float* filter_fc_b  = (const float*)d_in[9];
    float* out = (float*)d_out;

    const int smem_bytes = SMEM_FLOATS * (int)sizeof(float);
    static bool attr_set = false;   // host-side only; idempotent runtime attr
    if (!attr_set) {
        cudaFuncSetAttribute(fc_kernel,
                             cudaFuncAttributeMaxDynamicSharedMemorySize,
                             smem_bytes);
        attr_set = true;
    }

    pool_kernel<<<POOL_BLOCKS, 256>>>(x, fc_w, channel_fc_w, filter_fc_w,
                                      channel_fc_b, filter_fc_b,
                                      bn_gamma, bn_beta, bn_mean, bn_var);

    fc_kernel<<<B_SZ * 2, 512, smem_bytes>>>(
        fc_w, bn_gamma, bn_beta, bn_mean, bn_var,
        channel_fc_w, channel_fc_b, filter_fc_w, filter_fc_b, out);
}